// round 2
// baseline (speedup 1.0000x reference)
#include <cuda_runtime.h>

// Problem dims
#define DD 4096
#define MM 1024
#define LL 8192
#define NSLICE 32   // D-slices for the column pass partials

// ---------------- scratch (no allocation allowed; __device__ globals) --------
__device__ float g_sin[DD];                 // F_i @ input
__device__ float g_sq[DD];                  // F_q @ query
__device__ float g_qvec[MM];                // p[m] * scale[m]
__device__ float g_u[DD];                   // mem @ p
__device__ float g_v[DD];                   // prelu(s_q + H@u)
__device__ float g_part[3 * NSLICE * MM];   // column-pass partials [acc][slice][m]

// Selector so kernel_launch never needs cudaGetSymbolAddress (keeps capture trivially safe)
__device__ __forceinline__ float* resolve(int sel) {
    switch (sel) {
        case 1: return g_sin;
        case 2: return g_sq;
        case 3: return g_qvec;
        case 4: return g_u;
        case 5: return g_v;
    }
    return nullptr;
}

// ---------------- generic warp-per-row GEMV ---------------------------------
// out[r] = dot(A[r, :VECN], x)   (MODE 1: out[r] = prelu(bias[r] + dot, *a_ptr))
// 256 threads/block = 8 rows/block. float4 loads, 512B per warp per iteration.
template <int VECN, int MODE>
__global__ void gemv_warp(const float* __restrict__ A,
                          const float* __restrict__ xp, int xsel,
                          float* op, int osel,
                          int bsel, const float* __restrict__ a_ptr,
                          int nrows) {
    const float* __restrict__ x = xp ? xp : resolve(xsel);
    float* out = op ? op : resolve(osel);
    const int gw   = (blockIdx.x * blockDim.x + threadIdx.x) >> 5;
    const int lane = threadIdx.x & 31;
    if (gw >= nrows) return;

    const float4* __restrict__ a4 = reinterpret_cast<const float4*>(A) + (size_t)gw * (VECN / 4);
    const float4* __restrict__ x4 = reinterpret_cast<const float4*>(x);

    float acc0 = 0.f, acc1 = 0.f;   // 2 accumulators: break FFMA RAW chain
#pragma unroll 8
    for (int i = 0; i < VECN / 128; i++) {
        float4 a = a4[i * 32 + lane];
        float4 b = x4[i * 32 + lane];
        acc0 += a.x * b.x + a.y * b.y;
        acc1 += a.z * b.z + a.w * b.w;
    }
    float acc = acc0 + acc1;
#pragma unroll
    for (int o = 16; o; o >>= 1) acc += __shfl_down_sync(0xffffffffu, acc, o);

    if (lane == 0) {
        float val = acc;
        if (MODE == 1) {
            const float* bias = resolve(bsel);
            float t = bias[gw] + val;
            float a = *a_ptr;
            val = (t >= 0.f) ? t : a * t;
        }
        out[gw] = val;
    }
}

// ---------------- fused column pass over memory_nodes + keys -----------------
// For each column m, accumulate over a D-slice:
//   ag  = sum_d s_in[d] * (mem[d,m] + keys[d,m])   (gate logit)
//   ass = sum_d mem[d,m]^2                          (for column L2 norm)
//   aq  = sum_d s_q[d]  * mem[d,m]                  (attention logit, pre-scale)
// grid = (M/128, NSLICE), 256 threads: lane -> 4 columns (float4), warp -> d stride.
__global__ void k_colpass(const float* __restrict__ mem, const float* __restrict__ keys) {
    const int lane = threadIdx.x & 31;
    const int wp   = threadIdx.x >> 5;            // 0..7
    const int c4   = blockIdx.x * 32 + lane;      // float4 column index (M/4 = 256 total)
    const int slice = blockIdx.y;                 // 0..NSLICE-1
    const int d0 = slice * (DD / NSLICE);         // 128 rows per slice

    const float4* __restrict__ mem4 = reinterpret_cast<const float4*>(mem);
    const float4* __restrict__ key4 = reinterpret_cast<const float4*>(keys);

    float4 ag  = make_float4(0.f, 0.f, 0.f, 0.f);
    float4 ass = make_float4(0.f, 0.f, 0.f, 0.f);
    float4 aq  = make_float4(0.f, 0.f, 0.f, 0.f);

#pragma unroll 4
    for (int d = d0 + wp; d < d0 + DD / NSLICE; d += 8) {
        float4 mv = mem4[(size_t)d * (MM / 4) + c4];
        float4 kv = key4[(size_t)d * (MM / 4) + c4];
        float si = g_sin[d];
        float sq = g_sq[d];
        ag.x += si * (mv.x + kv.x);  ag.y += si * (mv.y + kv.y);
        ag.z += si * (mv.z + kv.z);  ag.w += si * (mv.w + kv.w);
        ass.x += mv.x * mv.x;  ass.y += mv.y * mv.y;
        ass.z += mv.z * mv.z;  ass.w += mv.w * mv.w;
        aq.x += sq * mv.x;  aq.y += sq * mv.y;
        aq.z += sq * mv.z;  aq.w += sq * mv.w;
    }

    __shared__ float4 s[3][8][32];
    s[0][wp][lane] = ag;
    s[1][wp][lane] = ass;
    s[2][wp][lane] = aq;
    __syncthreads();

    if (threadIdx.x < 32) {
        const int l = threadIdx.x;
#pragma unroll
        for (int a = 0; a < 3; a++) {
            float4 r = make_float4(0.f, 0.f, 0.f, 0.f);
#pragma unroll
            for (int t = 0; t < 8; t++) {
                float4 v = s[a][t][l];
                r.x += v.x; r.y += v.y; r.z += v.z; r.w += v.w;
            }
            reinterpret_cast<float4*>(g_part)[(size_t)(a * NSLICE + slice) * (MM / 4)
                                              + blockIdx.x * 32 + l] = r;
        }
    }
}

// ---------------- finalize: gate -> scale -> softmax -> qvec -----------------
// One block of 1024 threads (thread m handles column m).
__global__ void k_finalize() {
    const int m = threadIdx.x;
    float ag = 0.f, ass = 0.f, aq = 0.f;
#pragma unroll 8
    for (int s = 0; s < NSLICE; s++) {
        ag  += g_part[(0 * NSLICE + s) * MM + m];
        ass += g_part[(1 * NSLICE + s) * MM + m];
        aq  += g_part[(2 * NSLICE + s) * MM + m];
    }
    // gate
    float g = 1.f / (1.f + expf(-ag));
    float onep = 1.f + g;                       // in (1,2), always positive
    // column L2 norm of mem*(1+g) is (1+g)*sqrt(ass)
    float nrm = onep * sqrtf(ass);
    float scale = onep / fmaxf(nrm, 1e-12f);    // normalized-column multiplier
    float logit = scale * aq;

    __shared__ float red[32];
    __shared__ float bcast;
    const int lane = threadIdx.x & 31;
    const int wid  = threadIdx.x >> 5;

    // block max
    float v = logit;
#pragma unroll
    for (int o = 16; o; o >>= 1) v = fmaxf(v, __shfl_down_sync(0xffffffffu, v, o));
    if (lane == 0) red[wid] = v;
    __syncthreads();
    if (threadIdx.x == 0) {
        float mx = red[0];
#pragma unroll
        for (int t = 1; t < 32; t++) mx = fmaxf(mx, red[t]);
        bcast = mx;
    }
    __syncthreads();
    float e = expf(logit - bcast);

    // block sum
    v = e;
#pragma unroll
    for (int o = 16; o; o >>= 1) v += __shfl_down_sync(0xffffffffu, v, o);
    __syncthreads();
    if (lane == 0) red[wid] = v;
    __syncthreads();
    if (threadIdx.x == 0) {
        float sm = 0.f;
#pragma unroll
        for (int t = 0; t < 32; t++) sm += red[t];
        bcast = sm;
    }
    __syncthreads();

    g_qvec[m] = (e / bcast) * scale;   // p[m] * scale[m]
}

// ---------------- launch -----------------------------------------------------
extern "C" void kernel_launch(void* const* d_in, const int* in_sizes, int n_in,
                              void* d_out, int out_size) {
    const float* input = (const float*)d_in[0];
    const float* query = (const float*)d_in[1];
    const float* F_i   = (const float*)d_in[2];
    const float* F_q   = (const float*)d_in[3];
    const float* keys  = (const float*)d_in[4];
    const float* memn  = (const float*)d_in[5];
    // d_in[6..8] = U, V, W: dead code in the reference (cand is never used) — skipped.
    const float* R     = (const float*)d_in[9];
    const float* H     = (const float*)d_in[10];
    // d_in[11] = a_mem: only used by dead code — skipped.
    const float* a_out = (const float*)d_in[12];
    float* y = (float*)d_out;

    const int GB = (DD / 8);  // 512 blocks of 256 threads = 4096 warps = 4096 rows

    // s_in = F_i @ input ; s_q = F_q @ query   (268 MB — the dominant traffic)
    gemv_warp<LL, 0><<<GB, 256>>>(F_i, input, 0, nullptr, 1, 0, nullptr, DD);
    gemv_warp<LL, 0><<<GB, 256>>>(F_q, query, 0, nullptr, 2, 0, nullptr, DD);

    // fused gate/norm/logit column pass (32 MB, one read of mem+keys)
    k_colpass<<<dim3(MM / 128, NSLICE), 256>>>(memn, keys);

    // sigmoid gate, column scale, softmax -> qvec = p*scale
    k_finalize<<<1, 1024>>>();

    // u = memory_nodes @ qvec   (16 MB, L2-hot)
    gemv_warp<MM, 0><<<GB, 256>>>(memn, nullptr, 3, nullptr, 4, 0, nullptr, DD);

    // v = prelu(s_q + H @ u, a_out)   (64 MB)
    gemv_warp<DD, 1><<<GB, 256>>>(H, nullptr, 4, nullptr, 5, 2, a_out, DD);

    // y = R @ v   (64 MB)
    gemv_warp<DD, 0><<<GB, 256>>>(R, nullptr, 5, y, 0, 0, nullptr, DD);
}

// round 3
// speedup vs baseline: 1.0187x; 1.0187x over previous
#include <cuda_runtime.h>

// Problem dims
#define DD 4096
#define MM 1024
#define LL 8192
#define NSLICE 16   // D-slices for the column-pass partials

// ---------------- scratch (__device__ globals; no allocation allowed) --------
__device__ float g_sin[DD];                 // F_i @ input
__device__ float g_sq[DD];                  // F_q @ query
__device__ float g_qvec[MM];                // p[m] * scale[m]
__device__ float g_u[DD];                   // mem @ p
__device__ float g_v[DD];                   // prelu(s_q + H@u)
__device__ float g_part[3 * NSLICE * MM];   // column-pass partials [acc][slice][m]

__device__ __forceinline__ float* resolve(int sel) {
    switch (sel) {
        case 3: return g_qvec;
        case 4: return g_u;
        case 5: return g_v;
    }
    return nullptr;
}

// ---------------- stage 1: dual GEMV (F_i@input -> g_sin, F_q@query -> g_sq) -
// 2 warps per row, 4 rows per 256-thread block, grid = 2*DD/4 = 2048 blocks.
__global__ void k_stage1(const float* __restrict__ Fi, const float* __restrict__ Fq,
                         const float* __restrict__ input, const float* __restrict__ query) {
    const int w    = threadIdx.x >> 5;
    const int lane = threadIdx.x & 31;
    const int sub  = w >> 1;           // row within block (0..3)
    const int half = w & 1;            // which half of the row
    const int row  = blockIdx.x * 4 + sub;   // 0..8191 (F_i rows then F_q rows)

    const float* __restrict__ A = (row < DD) ? Fi : Fq;
    const float* __restrict__ x = (row < DD) ? input : query;
    const int r = (row < DD) ? row : row - DD;

    constexpr int HV4 = LL / 8;        // float4s per half-row = 1024
    const float4* __restrict__ a4 = reinterpret_cast<const float4*>(A)
                                    + (size_t)r * (LL / 4) + half * HV4;
    const float4* __restrict__ x4 = reinterpret_cast<const float4*>(x) + half * HV4;

    float acc0 = 0.f, acc1 = 0.f;
#pragma unroll 8
    for (int i = 0; i < HV4 / 32; i++) {     // 32 iters
        float4 a = a4[i * 32 + lane];
        float4 b = x4[i * 32 + lane];
        acc0 += a.x * b.x + a.y * b.y;
        acc1 += a.z * b.z + a.w * b.w;
    }
    float acc = acc0 + acc1;
#pragma unroll
    for (int o = 16; o; o >>= 1) acc += __shfl_down_sync(0xffffffffu, acc, o);

    __shared__ float s[8];
    if (lane == 0) s[w] = acc;
    __syncthreads();
    if (threadIdx.x < 4) {
        const int rr = blockIdx.x * 4 + threadIdx.x;
        float val = s[2 * threadIdx.x] + s[2 * threadIdx.x + 1];
        if (rr < DD) g_sin[rr] = val;
        else         g_sq[rr - DD] = val;
    }
}

// ---------------- generic split-2 GEMV ---------------------------------------
// out[r] = dot(A[r,:VECN], x).  MODE 1: out[r] = prelu(g_sq[r] + dot, *a_ptr).
// 2 warps/row, 4 rows/block, grid = nrows/4.
template <int VECN, int MODE>
__global__ void gemv2(const float* __restrict__ A,
                      int xsel, float* op, int osel,
                      const float* __restrict__ a_ptr) {
    const float* __restrict__ x = resolve(xsel);
    float* out = op ? op : resolve(osel);
    const int w    = threadIdx.x >> 5;
    const int lane = threadIdx.x & 31;
    const int sub  = w >> 1;
    const int half = w & 1;
    const int row  = blockIdx.x * 4 + sub;

    constexpr int HV4 = VECN / 8;      // float4s per half-row
    const float4* __restrict__ a4 = reinterpret_cast<const float4*>(A)
                                    + (size_t)row * (VECN / 4) + half * HV4;
    const float4* __restrict__ x4 = reinterpret_cast<const float4*>(x) + half * HV4;

    float acc0 = 0.f, acc1 = 0.f;
#pragma unroll
    for (int i = 0; i < HV4 / 32; i++) {
        float4 a = a4[i * 32 + lane];
        float4 b = x4[i * 32 + lane];
        acc0 += a.x * b.x + a.y * b.y;
        acc1 += a.z * b.z + a.w * b.w;
    }
    float acc = acc0 + acc1;
#pragma unroll
    for (int o = 16; o; o >>= 1) acc += __shfl_down_sync(0xffffffffu, acc, o);

    __shared__ float s[8];
    if (lane == 0) s[w] = acc;
    __syncthreads();
    if (threadIdx.x < 4) {
        const int rr = blockIdx.x * 4 + threadIdx.x;
        float val = s[2 * threadIdx.x] + s[2 * threadIdx.x + 1];
        if (MODE == 1) {
            float t = g_sq[rr] + val;
            float a = *a_ptr;
            val = (t >= 0.f) ? t : a * t;
        }
        out[rr] = val;
    }
}

// ---------------- fused column pass over memory_nodes + keys -----------------
// Per column m over a D-slice:
//   ag  = sum_d s_in[d]*(mem[d,m]+keys[d,m])   gate logit
//   ass = sum_d mem[d,m]^2                      column L2 norm
//   aq  = sum_d s_q[d]*mem[d,m]                 attention logit (pre-scale)
// grid = (M/128, NSLICE) = (8,16) = 128 blocks, 256 threads.
__global__ void k_colpass(const float* __restrict__ mem, const float* __restrict__ keys) {
    const int lane  = threadIdx.x & 31;
    const int wp    = threadIdx.x >> 5;          // 0..7
    const int c4    = blockIdx.x * 32 + lane;    // float4 column index
    const int slice = blockIdx.y;
    const int d0    = slice * (DD / NSLICE);     // 256 rows per slice

    const float4* __restrict__ mem4 = reinterpret_cast<const float4*>(mem);
    const float4* __restrict__ key4 = reinterpret_cast<const float4*>(keys);

    float4 ag  = make_float4(0.f, 0.f, 0.f, 0.f);
    float4 ass = make_float4(0.f, 0.f, 0.f, 0.f);
    float4 aq  = make_float4(0.f, 0.f, 0.f, 0.f);

#pragma unroll 4
    for (int d = d0 + wp; d < d0 + DD / NSLICE; d += 8) {
        float4 mv = mem4[(size_t)d * (MM / 4) + c4];
        float4 kv = key4[(size_t)d * (MM / 4) + c4];
        float si = g_sin[d];
        float sq = g_sq[d];
        ag.x += si * (mv.x + kv.x);  ag.y += si * (mv.y + kv.y);
        ag.z += si * (mv.z + kv.z);  ag.w += si * (mv.w + kv.w);
        ass.x += mv.x * mv.x;  ass.y += mv.y * mv.y;
        ass.z += mv.z * mv.z;  ass.w += mv.w * mv.w;
        aq.x += sq * mv.x;  aq.y += sq * mv.y;
        aq.z += sq * mv.z;  aq.w += sq * mv.w;
    }

    __shared__ float4 s[3][8][32];
    s[0][wp][lane] = ag;
    s[1][wp][lane] = ass;
    s[2][wp][lane] = aq;
    __syncthreads();

    if (threadIdx.x < 32) {
        const int l = threadIdx.x;
#pragma unroll
        for (int a = 0; a < 3; a++) {
            float4 r = make_float4(0.f, 0.f, 0.f, 0.f);
#pragma unroll
            for (int t = 0; t < 8; t++) {
                float4 v = s[a][t][l];
                r.x += v.x; r.y += v.y; r.z += v.z; r.w += v.w;
            }
            reinterpret_cast<float4*>(g_part)[(size_t)(a * NSLICE + slice) * (MM / 4)
                                              + blockIdx.x * 32 + l] = r;
        }
    }
}

// ---------------- finalize: gate -> scale -> softmax -> qvec -----------------
// 1 block, 256 threads; thread t handles columns 4t..4t+3 (float4 everywhere).
// 48 independent float4 loads per thread -> high MLP.
__global__ void k_finalize() {
    const int t    = threadIdx.x;           // 0..255
    const int lane = t & 31;
    const int wid  = t >> 5;                // 0..7
    const float4* __restrict__ p4 = reinterpret_cast<const float4*>(g_part);

    float4 ag  = make_float4(0.f, 0.f, 0.f, 0.f);
    float4 ass = make_float4(0.f, 0.f, 0.f, 0.f);
    float4 aq  = make_float4(0.f, 0.f, 0.f, 0.f);
#pragma unroll
    for (int s = 0; s < NSLICE; s++) {
        float4 v0 = p4[(0 * NSLICE + s) * (MM / 4) + t];
        float4 v1 = p4[(1 * NSLICE + s) * (MM / 4) + t];
        float4 v2 = p4[(2 * NSLICE + s) * (MM / 4) + t];
        ag.x += v0.x; ag.y += v0.y; ag.z += v0.z; ag.w += v0.w;
        ass.x += v1.x; ass.y += v1.y; ass.z += v1.z; ass.w += v1.w;
        aq.x += v2.x; aq.y += v2.y; aq.z += v2.z; aq.w += v2.w;
    }

    float l[4], sc[4];
    {
        float agv[4]  = {ag.x, ag.y, ag.z, ag.w};
        float assv[4] = {ass.x, ass.y, ass.z, ass.w};
        float aqv[4]  = {aq.x, aq.y, aq.z, aq.w};
#pragma unroll
        for (int i = 0; i < 4; i++) {
            float g    = 1.f / (1.f + expf(-agv[i]));
            float onep = 1.f + g;                       // (1,2) > 0
            float nrm  = onep * sqrtf(assv[i]);         // ||mem_col*(1+g)||
            sc[i]      = onep / fmaxf(nrm, 1e-12f);
            l[i]       = sc[i] * aqv[i];
        }
    }

    __shared__ float red[8];
    __shared__ float bc;

    // block max
    float v = fmaxf(fmaxf(l[0], l[1]), fmaxf(l[2], l[3]));
#pragma unroll
    for (int o = 16; o; o >>= 1) v = fmaxf(v, __shfl_down_sync(0xffffffffu, v, o));
    if (lane == 0) red[wid] = v;
    __syncthreads();
    if (t == 0) {
        float mx = red[0];
#pragma unroll
        for (int i = 1; i < 8; i++) mx = fmaxf(mx, red[i]);
        bc = mx;
    }
    __syncthreads();
    const float mx = bc;

    float e[4];
#pragma unroll
    for (int i = 0; i < 4; i++) e[i] = expf(l[i] - mx);

    // block sum
    v = e[0] + e[1] + e[2] + e[3];
#pragma unroll
    for (int o = 16; o; o >>= 1) v += __shfl_down_sync(0xffffffffu, v, o);
    __syncthreads();
    if (lane == 0) red[wid] = v;
    __syncthreads();
    if (t == 0) {
        float sm = 0.f;
#pragma unroll
        for (int i = 0; i < 8; i++) sm += red[i];
        bc = sm;
    }
    __syncthreads();
    const float inv = 1.f / bc;

    float4 q;
    q.x = e[0] * inv * sc[0];
    q.y = e[1] * inv * sc[1];
    q.z = e[2] * inv * sc[2];
    q.w = e[3] * inv * sc[3];
    reinterpret_cast<float4*>(g_qvec)[t] = q;
}

// ---------------- launch -----------------------------------------------------
extern "C" void kernel_launch(void* const* d_in, const int* in_sizes, int n_in,
                              void* d_out, int out_size) {
    const float* input = (const float*)d_in[0];
    const float* query = (const float*)d_in[1];
    const float* F_i   = (const float*)d_in[2];
    const float* F_q   = (const float*)d_in[3];
    const float* keys  = (const float*)d_in[4];
    const float* memn  = (const float*)d_in[5];
    // d_in[6..8] = U, V, W: dead code in the reference (cand unused) — skipped.
    const float* R     = (const float*)d_in[9];
    const float* H     = (const float*)d_in[10];
    // d_in[11] = a_mem: dead code — skipped.
    const float* a_out = (const float*)d_in[12];
    float* y = (float*)d_out;

    // s_in & s_q in one kernel (268 MB — dominant traffic), 2 warps/row
    k_stage1<<<2 * DD / 4, 256>>>(F_i, F_q, input, query);

    // fused gate/norm/logit column pass (32 MB, single read of mem+keys)
    k_colpass<<<dim3(MM / 128, NSLICE), 256>>>(memn, keys);

    // sigmoid gate, column scale, softmax -> qvec = p*scale
    k_finalize<<<1, 256>>>();

    // u = memory_nodes @ qvec   (16 MB, L2-hot from colpass)
    gemv2<MM, 0><<<DD / 4, 256>>>(memn, 3, nullptr, 4, nullptr);

    // v = prelu(s_q + H @ u, a_out)   (64 MB)
    gemv2<DD, 1><<<DD / 4, 256>>>(H, 4, nullptr, 5, a_out);

    // y = R @ v   (64 MB)
    gemv2<DD, 0><<<DD / 4, 256>>>(R, 5, y, 0, nullptr);
}

// round 5
// speedup vs baseline: 1.0827x; 1.0628x over previous
#include <cuda_runtime.h>

#define DD 4096
#define MM 1024
#define LL 8192
#define NB 512        // persistent grid; __launch_bounds__(256,4): 148*4=592 >= 512 resident
#define NSLICE 128    // colpass D-slices (32 rows each)

// ---------------- scratch (__device__ globals; no allocation allowed) --------
__device__ float g_sin[DD];
__device__ float g_sq[DD];
__device__ float g_qvec[MM];                 // p[m] * scale[m]
__device__ float g_u[DD];
__device__ float g_v[DD];
__device__ float g_part[3 * NSLICE * MM];    // colpass partials [acc][slice][m]
__device__ unsigned g_count = 0;             // monotone across replays (relative compares only)
__device__ unsigned g_phase = 0;

// ---------------- grid-wide barrier (all NB blocks resident) ------------------
__device__ __forceinline__ void gridbar() {
    __syncthreads();
    if (threadIdx.x == 0) {
        __threadfence();                      // release: publish this block's stage writes
        volatile unsigned* ph = &g_phase;
        unsigned p = *ph;                     // snapshot before arriving (phase cannot advance
                                              // past this barrier without our arrival)
        unsigned old = atomicAdd(&g_count, 1u);
        if ((old + 1u) % NB == 0u) {
            atomicAdd(&g_phase, 1u);          // release the barrier
        } else {
            while (*ph == p) __nanosleep(64);
        }
        __threadfence();                      // acquire
    }
    __syncthreads();
}

// ---------------- warp dot ----------------------------------------------------
// CS: evict-first streaming loads on A (stream-once matrices, protect mem/keys in L2).
// XC: 1 -> x is kernel-constant (safe for __ldg); 0 -> x written THIS kernel by
//     other SMs: MUST use plain coherent loads (the R3 bug was __ldg here).
template <int N4, int CS, int XC>
__device__ __forceinline__ float warp_dot(const float4* __restrict__ a4,
                                          const float4* x4, int lane) {
    float acc0 = 0.f, acc1 = 0.f;
#pragma unroll 8
    for (int i = 0; i < N4 / 32; i++) {
        float4 a = CS ? __ldcs(a4 + i * 32 + lane) : *(a4 + i * 32 + lane);
        float4 b = XC ? __ldg(x4 + i * 32 + lane) : *(x4 + i * 32 + lane);
        acc0 += a.x * b.x + a.y * b.y;
        acc1 += a.z * b.z + a.w * b.w;
    }
    float acc = acc0 + acc1;
#pragma unroll
    for (int o = 16; o; o >>= 1) acc += __shfl_down_sync(0xffffffffu, acc, o);
    return acc;
}

// ---------------- persistent mega-kernel -------------------------------------
__global__ __launch_bounds__(256, 4) void k_mega(
    const float* __restrict__ Fi, const float* __restrict__ Fq,
    const float* __restrict__ input, const float* __restrict__ query,
    const float* __restrict__ mem, const float* __restrict__ keys,
    const float* __restrict__ H, const float* __restrict__ R,
    const float* __restrict__ a_out, float* __restrict__ y)
{
    const int tid  = threadIdx.x;
    const int w    = tid >> 5;
    const int lane = tid & 31;
    const int bid  = blockIdx.x;
    const int gwarp = bid * 8 + w;            // 0..4095

    __shared__ float4 s4[3][8][32];           // colpass cross-warp reduce (12 KB)
    __shared__ float red[8];
    __shared__ float bc;

    // ===== stage 1: g_sin = F_i@input, g_sq = F_q@query (268 MB, dominant) =====
    {
        const float4* in4 = reinterpret_cast<const float4*>(input);
        const float4* qr4 = reinterpret_cast<const float4*>(query);
        {
            const float4* a4 = reinterpret_cast<const float4*>(Fi) + (size_t)gwarp * (LL / 4);
            float acc = warp_dot<LL / 4, 1, 1>(a4, in4, lane);
            if (lane == 0) g_sin[gwarp] = acc;
        }
        {
            const float4* a4 = reinterpret_cast<const float4*>(Fq) + (size_t)gwarp * (LL / 4);
            float acc = warp_dot<LL / 4, 1, 1>(a4, qr4, lane);
            if (lane == 0) g_sq[gwarp] = acc;
        }
    }
    gridbar();

    // ===== colpass: per-column gate logit, sumsq, attention logit (32 MB) =====
    // 1024 tasks = (cblk 0..7) x (slice 0..127); 2 tasks per block.
    {
        const float4* mem4 = reinterpret_cast<const float4*>(mem);
        const float4* key4 = reinterpret_cast<const float4*>(keys);
#pragma unroll
        for (int rep = 0; rep < 2; rep++) {
            const int task  = rep * NB + bid;
            const int cblk  = task & 7;
            const int slice = task >> 3;
            const int d0    = slice * 32;
            const int c4    = cblk * 32 + lane;

            float4 ag  = make_float4(0.f, 0.f, 0.f, 0.f);
            float4 ass = make_float4(0.f, 0.f, 0.f, 0.f);
            float4 aq  = make_float4(0.f, 0.f, 0.f, 0.f);
#pragma unroll
            for (int j = 0; j < 4; j++) {
                const int d = d0 + w + j * 8;
                float4 mv = mem4[(size_t)d * (MM / 4) + c4];
                float4 kv = key4[(size_t)d * (MM / 4) + c4];
                float si = g_sin[d];     // plain loads: written this kernel, post-barrier
                float sq = g_sq[d];
                ag.x += si * (mv.x + kv.x);  ag.y += si * (mv.y + kv.y);
                ag.z += si * (mv.z + kv.z);  ag.w += si * (mv.w + kv.w);
                ass.x += mv.x * mv.x;  ass.y += mv.y * mv.y;
                ass.z += mv.z * mv.z;  ass.w += mv.w * mv.w;
                aq.x += sq * mv.x;  aq.y += sq * mv.y;
                aq.z += sq * mv.z;  aq.w += sq * mv.w;
            }
            s4[0][w][lane] = ag;
            s4[1][w][lane] = ass;
            s4[2][w][lane] = aq;
            __syncthreads();
            if (tid < 32) {
#pragma unroll
                for (int a = 0; a < 3; a++) {
                    float4 r = make_float4(0.f, 0.f, 0.f, 0.f);
#pragma unroll
                    for (int t = 0; t < 8; t++) {
                        float4 v = s4[a][t][tid];
                        r.x += v.x; r.y += v.y; r.z += v.z; r.w += v.w;
                    }
                    reinterpret_cast<float4*>(g_part)[(size_t)(a * NSLICE + slice) * (MM / 4)
                                                      + cblk * 32 + tid] = r;
                }
            }
            __syncthreads();
        }
    }
    gridbar();

    // ===== finalize (block 0): gate -> scale -> softmax -> qvec =====
    if (bid == 0) {
        const float4* p4 = reinterpret_cast<const float4*>(g_part);
        float4 ag  = make_float4(0.f, 0.f, 0.f, 0.f);
        float4 ass = make_float4(0.f, 0.f, 0.f, 0.f);
        float4 aq  = make_float4(0.f, 0.f, 0.f, 0.f);
#pragma unroll 8
        for (int s = 0; s < NSLICE; s++) {
            float4 v0 = p4[(0 * NSLICE + s) * (MM / 4) + tid];
            float4 v1 = p4[(1 * NSLICE + s) * (MM / 4) + tid];
            float4 v2 = p4[(2 * NSLICE + s) * (MM / 4) + tid];
            ag.x += v0.x; ag.y += v0.y; ag.z += v0.z; ag.w += v0.w;
            ass.x += v1.x; ass.y += v1.y; ass.z += v1.z; ass.w += v1.w;
            aq.x += v2.x; aq.y += v2.y; aq.z += v2.z; aq.w += v2.w;
        }
        float l[4], sc[4];
        {
            float agv[4]  = {ag.x, ag.y, ag.z, ag.w};
            float assv[4] = {ass.x, ass.y, ass.z, ass.w};
            float aqv[4]  = {aq.x, aq.y, aq.z, aq.w};
#pragma unroll
            for (int i = 0; i < 4; i++) {
                float g    = 1.f / (1.f + expf(-agv[i]));
                float onep = 1.f + g;                    // (1,2) > 0
                float nrm  = onep * sqrtf(assv[i]);      // ||mem_col*(1+g)||
                sc[i]      = onep / fmaxf(nrm, 1e-12f);
                l[i]       = sc[i] * aqv[i];
            }
        }
        // block max
        float v = fmaxf(fmaxf(l[0], l[1]), fmaxf(l[2], l[3]));
#pragma unroll
        for (int o = 16; o; o >>= 1) v = fmaxf(v, __shfl_down_sync(0xffffffffu, v, o));
        if (lane == 0) red[w] = v;
        __syncthreads();
        if (tid == 0) {
            float mx = red[0];
#pragma unroll
            for (int i = 1; i < 8; i++) mx = fmaxf(mx, red[i]);
            bc = mx;
        }
        __syncthreads();
        const float mx = bc;
        float e[4];
#pragma unroll
        for (int i = 0; i < 4; i++) e[i] = expf(l[i] - mx);
        // block sum
        v = e[0] + e[1] + e[2] + e[3];
#pragma unroll
        for (int o = 16; o; o >>= 1) v += __shfl_down_sync(0xffffffffu, v, o);
        __syncthreads();
        if (lane == 0) red[w] = v;
        __syncthreads();
        if (tid == 0) {
            float sm = 0.f;
#pragma unroll
            for (int i = 0; i < 8; i++) sm += red[i];
            bc = sm;
        }
        __syncthreads();
        const float inv = 1.f / bc;
        float4 q;
        q.x = e[0] * inv * sc[0];
        q.y = e[1] * inv * sc[1];
        q.z = e[2] * inv * sc[2];
        q.w = e[3] * inv * sc[3];
        reinterpret_cast<float4*>(g_qvec)[tid] = q;
    }
    gridbar();

    // ===== u = memory_nodes @ qvec (16 MB, L2-hot; warp-per-row) =====
    {
        const float4* a4 = reinterpret_cast<const float4*>(mem) + (size_t)gwarp * (MM / 4);
        const float4* x4 = reinterpret_cast<const float4*>(g_qvec);
        float acc = warp_dot<MM / 4, 0, 0>(a4, x4, lane);   // XC=0: g_qvec mutated this kernel
        if (lane == 0) g_u[gwarp] = acc;
    }
    gridbar();

    // ===== v = prelu(s_q + H @ u) (64 MB; warp-per-row) =====
    {
        const float4* a4 = reinterpret_cast<const float4*>(H) + (size_t)gwarp * (DD / 4);
        const float4* x4 = reinterpret_cast<const float4*>(g_u);
        float acc = warp_dot<DD / 4, 1, 0>(a4, x4, lane);   // XC=0: g_u mutated this kernel
        if (lane == 0) {
            float t = g_sq[gwarp] + acc;
            float a = *a_out;
            g_v[gwarp] = (t >= 0.f) ? t : a * t;
        }
    }
    gridbar();

    // ===== y = R @ v (64 MB; warp-per-row) =====
    {
        const float4* a4 = reinterpret_cast<const float4*>(R) + (size_t)gwarp * (DD / 4);
        const float4* x4 = reinterpret_cast<const float4*>(g_v);
        float acc = warp_dot<DD / 4, 1, 0>(a4, x4, lane);   // XC=0: g_v mutated this kernel
        if (lane == 0) y[gwarp] = acc;
    }
}

// ---------------- launch -----------------------------------------------------
extern "C" void kernel_launch(void* const* d_in, const int* in_sizes, int n_in,
                              void* d_out, int out_size) {
    const float* input = (const float*)d_in[0];
    const float* query = (const float*)d_in[1];
    const float* F_i   = (const float*)d_in[2];
    const float* F_q   = (const float*)d_in[3];
    const float* keys  = (const float*)d_in[4];
    const float* memn  = (const float*)d_in[5];
    // d_in[6..8] = U, V, W: dead code (cand unused) — skipped.
    const float* R     = (const float*)d_in[9];
    const float* H     = (const float*)d_in[10];
    // d_in[11] = a_mem: dead code — skipped.
    const float* a_out = (const float*)d_in[12];
    float* y = (float*)d_out;

    k_mega<<<NB, 256>>>(F_i, F_q, input, query, memn, keys, H, R, a_out, y);
}